// round 3
// baseline (speedup 1.0000x reference)
#include <cuda_runtime.h>
#include <cstdint>
#include <math.h>

// Problem constants
#define B_  4
#define S_  2048
#define D_  1024
#define H_  16
#define DH_ 64
#define MROWS (B_ * S_)     // 8192

typedef unsigned long long ull;

// ---------------- packed f32x2 helpers (FFMA2 only reachable via PTX) -------
__device__ __forceinline__ ull pk2(float a, float b) {
    ull r; asm("mov.b64 %0, {%1, %2};" : "=l"(r) : "f"(a), "f"(b)); return r;
}
__device__ __forceinline__ float2 up2(ull v) {
    float2 r; asm("mov.b64 {%0, %1}, %2;" : "=f"(r.x), "=f"(r.y) : "l"(v)); return r;
}
__device__ __forceinline__ ull f2fma(ull a, ull b, ull c) {
    ull d; asm("fma.rn.f32x2 %0, %1, %2, %3;" : "=l"(d) : "l"(a), "l"(b), "l"(c)); return d;
}
__device__ __forceinline__ ull f2mul(ull a, ull b) {
    ull d; asm("mul.rn.f32x2 %0, %1, %2;" : "=l"(d) : "l"(a), "l"(b)); return d;
}

// ---------------- scratch (device globals: no runtime allocation allowed) ---
__device__ float g_q[MROWS * D_];
__device__ float g_k[MROWS * D_];
__device__ float g_v[MROWS * D_];
__device__ float g_o[MROWS * D_];

// ---------------------------------------------------------------------------
// SGEMM:  C[M,N] = A[M,K] * W[N,K]^T   (both K-contiguous, fp32)
// BM=BN=128, BK=16, 256 threads, 8x8 per thread, packed f32x2 along N.
// ---------------------------------------------------------------------------
__global__ __launch_bounds__(256) void sgemm_nt(
    const float* __restrict__ A, const float* __restrict__ W,
    float* __restrict__ C, int M, int N, int K)
{
    __shared__ __align__(16) float As[16][128];
    __shared__ __align__(16) float Bs[16][128];

    const int tid   = threadIdx.x;
    const int m0    = (tid >> 4) << 3;   // 0..120
    const int n0    = (tid & 15) << 3;   // 0..120
    const int mBase = blockIdx.y * 128;
    const int nBase = blockIdx.x * 128;

    const int arow = tid >> 2;           // 0..63 (+64 on second pass)
    const int ac4  = (tid & 3) << 2;     // 0,4,8,12

    ull acc[8][4];
#pragma unroll
    for (int i = 0; i < 8; i++)
#pragma unroll
        for (int j = 0; j < 4; j++) acc[i][j] = 0ULL;

    for (int kb = 0; kb < K; kb += 16) {
#pragma unroll
        for (int i = 0; i < 2; i++) {
            int r = arow + i * 64;
            float4 va = *(const float4*)(A + (size_t)(mBase + r) * K + kb + ac4);
            As[ac4 + 0][r] = va.x; As[ac4 + 1][r] = va.y;
            As[ac4 + 2][r] = va.z; As[ac4 + 3][r] = va.w;
            float4 vb = *(const float4*)(W + (size_t)(nBase + r) * K + kb + ac4);
            Bs[ac4 + 0][r] = vb.x; Bs[ac4 + 1][r] = vb.y;
            Bs[ac4 + 2][r] = vb.z; Bs[ac4 + 3][r] = vb.w;
        }
        __syncthreads();
#pragma unroll
        for (int k = 0; k < 16; k++) {
            float4 a0 = *(const float4*)&As[k][m0];
            float4 a1 = *(const float4*)&As[k][m0 + 4];
            ull b0 = *(const ull*)&Bs[k][n0 + 0];
            ull b1 = *(const ull*)&Bs[k][n0 + 2];
            ull b2 = *(const ull*)&Bs[k][n0 + 4];
            ull b3 = *(const ull*)&Bs[k][n0 + 6];
            float av[8] = {a0.x, a0.y, a0.z, a0.w, a1.x, a1.y, a1.z, a1.w};
#pragma unroll
            for (int i = 0; i < 8; i++) {
                ull a2 = pk2(av[i], av[i]);
                acc[i][0] = f2fma(a2, b0, acc[i][0]);
                acc[i][1] = f2fma(a2, b1, acc[i][1]);
                acc[i][2] = f2fma(a2, b2, acc[i][2]);
                acc[i][3] = f2fma(a2, b3, acc[i][3]);
            }
        }
        __syncthreads();
    }

#pragma unroll
    for (int i = 0; i < 8; i++) {
        float2 c0 = up2(acc[i][0]), c1 = up2(acc[i][1]);
        float2 c2 = up2(acc[i][2]), c3 = up2(acc[i][3]);
        float* cp = C + (size_t)(mBase + m0 + i) * N + nBase + n0;
        *(float4*)cp       = make_float4(c0.x, c0.y, c1.x, c1.y);
        *(float4*)(cp + 4) = make_float4(c2.x, c2.y, c3.x, c3.y);
    }
}

// ---------------------------------------------------------------------------
// Flash attention, fp32, causal. One q-row per thread (128 rows/CTA),
// K/V tiles 64x64 in smem (broadcast LDS reads), online softmax in 32-chunks.
// grid = (S/128, B*H), 128 threads.
// ---------------------------------------------------------------------------
__global__ __launch_bounds__(128) void flash_kernel(
    const float* __restrict__ Qp, const float* __restrict__ Kp,
    const float* __restrict__ Vp, float* __restrict__ Op)
{
    __shared__ __align__(16) float Ks[64 * 64];
    __shared__ __align__(16) float Vs[64 * 64];

    const int qt  = blockIdx.x;          // 0..15
    const int bh  = blockIdx.y;          // 0..63
    const int b   = bh >> 4;
    const int h   = bh & 15;
    const int tid = threadIdx.x;         // 0..127
    const int qs  = qt * 128 + tid;      // global q position

    const size_t rowOff = ((size_t)(b * S_ + qs)) * D_ + h * DH_;

    ull q2[32];
#pragma unroll
    for (int i = 0; i < 32; i++) q2[i] = *(const ull*)(Qp + rowOff + 2 * i);

    ull o2[32];
#pragma unroll
    for (int i = 0; i < 32; i++) o2[i] = 0ULL;

    float m = -INFINITY, l = 0.f;

    const int nkt = 2 * qt + 2;          // causal: k-tiles 0..2qt+1
    for (int kt = 0; kt < nkt; kt++) {
        const float* kb_ = Kp + ((size_t)(b * S_ + kt * 64)) * D_ + h * DH_;
        const float* vb_ = Vp + ((size_t)(b * S_ + kt * 64)) * D_ + h * DH_;
#pragma unroll
        for (int i = 0; i < 8; i++) {
            int f = i * 128 + tid;
            int r = f >> 4, c4 = (f & 15) << 2;
            *(float4*)(Ks + r * 64 + c4) = *(const float4*)(kb_ + (size_t)r * D_ + c4);
            *(float4*)(Vs + r * 64 + c4) = *(const float4*)(vb_ + (size_t)r * D_ + c4);
        }
        __syncthreads();

#pragma unroll
        for (int c = 0; c < 2; c++) {
            int kbase = kt * 64 + c * 32;
            if (kbase <= qs) {           // warp-uniform (32-aligned boundaries)
                float s[32];
#pragma unroll
                for (int j = 0; j < 32; j++) {
                    const ull* kr = (const ull*)(Ks + (c * 32 + j) * 64);
                    ull accA = 0ULL, accB = 0ULL;
#pragma unroll
                    for (int d = 0; d < 32; d += 2) {
                        accA = f2fma(q2[d],     kr[d],     accA);
                        accB = f2fma(q2[d + 1], kr[d + 1], accB);
                    }
                    float2 ra = up2(accA), rb = up2(accB);
                    float sv = (ra.x + ra.y + rb.x + rb.y) * 0.125f;
                    s[j] = (kbase + j > qs) ? -INFINITY : sv;
                }
                float mx = m;
#pragma unroll
                for (int j = 0; j < 32; j++) mx = fmaxf(mx, s[j]);
                float corr = __expf(m - mx);
                float ssum = 0.f;
#pragma unroll
                for (int j = 0; j < 32; j++) { s[j] = __expf(s[j] - mx); ssum += s[j]; }
                l = l * corr + ssum;
                m = mx;
                ull c2 = pk2(corr, corr);
#pragma unroll
                for (int d = 0; d < 32; d++) o2[d] = f2mul(o2[d], c2);
#pragma unroll
                for (int j = 0; j < 32; j++) {
                    ull p2 = pk2(s[j], s[j]);
                    const ull* vr = (const ull*)(Vs + (c * 32 + j) * 64);
#pragma unroll
                    for (int d = 0; d < 32; d++) o2[d] = f2fma(p2, vr[d], o2[d]);
                }
            }
        }
        __syncthreads();
    }

    float inv = 1.0f / l;
    ull i2 = pk2(inv, inv);
    float* orow = Op + rowOff;
#pragma unroll
    for (int d = 0; d < 32; d++) {
        float2 r = up2(f2mul(o2[d], i2));
        *(float2*)(orow + 2 * d) = r;
    }
}

// ---------------------------------------------------------------------------
extern "C" void kernel_launch(void* const* d_in, const int* in_sizes, int n_in,
                              void* d_out, int out_size)
{
    const float* Q  = (const float*)d_in[0];
    const float* Kx = (const float*)d_in[1];
    const float* Vx = (const float*)d_in[2];
    const float* Wq = (const float*)d_in[3];
    const float* Wk = (const float*)d_in[4];
    const float* Wv = (const float*)d_in[5];
    const float* Wo = (const float*)d_in[6];
    float* out = (float*)d_out;

    float *q, *k, *v, *o;
    cudaGetSymbolAddress((void**)&q, g_q);
    cudaGetSymbolAddress((void**)&k, g_k);
    cudaGetSymbolAddress((void**)&v, g_v);
    cudaGetSymbolAddress((void**)&o, g_o);

    dim3 gg(D_ / 128, MROWS / 128);   // (8, 64)
    sgemm_nt<<<gg, 256>>>(Q,  Wq, q, MROWS, D_, D_);
    sgemm_nt<<<gg, 256>>>(Kx, Wk, k, MROWS, D_, D_);
    sgemm_nt<<<gg, 256>>>(Vx, Wv, v, MROWS, D_, D_);

    flash_kernel<<<dim3(S_ / 128, B_ * H_), 128>>>(q, k, v, o);

    sgemm_nt<<<gg, 256>>>(o, Wo, out, MROWS, D_, D_);
}

// round 8
// speedup vs baseline: 1.0093x; 1.0093x over previous
#include <cuda_runtime.h>
#include <cstdint>
#include <math.h>

// Problem constants
#define B_  4
#define S_  2048
#define D_  1024
#define H_  16
#define DH_ 64
#define MROWS (B_ * S_)     // 8192

typedef unsigned long long ull;

// ---------------- packed f32x2 helpers (FFMA2 only reachable via PTX) -------
__device__ __forceinline__ ull pk2(float a, float b) {
    ull r; asm("mov.b64 %0, {%1, %2};" : "=l"(r) : "f"(a), "f"(b)); return r;
}
__device__ __forceinline__ float2 up2(ull v) {
    float2 r; asm("mov.b64 {%0, %1}, %2;" : "=f"(r.x), "=f"(r.y) : "l"(v)); return r;
}
__device__ __forceinline__ ull f2fma(ull a, ull b, ull c) {
    ull d; asm("fma.rn.f32x2 %0, %1, %2, %3;" : "=l"(d) : "l"(a), "l"(b), "l"(c)); return d;
}
__device__ __forceinline__ ull f2mul(ull a, ull b) {
    ull d; asm("mul.rn.f32x2 %0, %1, %2;" : "=l"(d) : "l"(a), "l"(b)); return d;
}

// ---------------- scratch (device globals: no runtime allocation allowed) ---
__device__ float g_q[MROWS * D_];
__device__ float g_k[MROWS * D_];
__device__ float g_v[MROWS * D_];
__device__ float g_o[MROWS * D_];

// ---------------------------------------------------------------------------
// SGEMM:  C[M,N] = A[M,K] * W[N,K]^T   (both K-contiguous, fp32)
// BM=BN=128, BK=16, 256 threads, 8x8 per thread, packed f32x2 along N.
// ---------------------------------------------------------------------------
__global__ __launch_bounds__(256) void sgemm_nt(
    const float* __restrict__ A, const float* __restrict__ W,
    float* __restrict__ C, int M, int N, int K)
{
    __shared__ __align__(16) float As[16][128];
    __shared__ __align__(16) float Bs[16][128];

    const int tid   = threadIdx.x;
    const int m0    = (tid >> 4) << 3;   // 0..120
    const int n0    = (tid & 15) << 3;   // 0..120
    const int mBase = blockIdx.y * 128;
    const int nBase = blockIdx.x * 128;

    const int arow = tid >> 2;           // 0..63 (+64 on second pass)
    const int ac4  = (tid & 3) << 2;     // 0,4,8,12

    ull acc[8][4];
#pragma unroll
    for (int i = 0; i < 8; i++)
#pragma unroll
        for (int j = 0; j < 4; j++) acc[i][j] = 0ULL;

    for (int kb = 0; kb < K; kb += 16) {
#pragma unroll
        for (int i = 0; i < 2; i++) {
            int r = arow + i * 64;
            float4 va = *(const float4*)(A + (size_t)(mBase + r) * K + kb + ac4);
            As[ac4 + 0][r] = va.x; As[ac4 + 1][r] = va.y;
            As[ac4 + 2][r] = va.z; As[ac4 + 3][r] = va.w;
            float4 vb = *(const float4*)(W + (size_t)(nBase + r) * K + kb + ac4);
            Bs[ac4 + 0][r] = vb.x; Bs[ac4 + 1][r] = vb.y;
            Bs[ac4 + 2][r] = vb.z; Bs[ac4 + 3][r] = vb.w;
        }
        __syncthreads();
#pragma unroll
        for (int k = 0; k < 16; k++) {
            float4 a0 = *(const float4*)&As[k][m0];
            float4 a1 = *(const float4*)&As[k][m0 + 4];
            ull b0 = *(const ull*)&Bs[k][n0 + 0];
            ull b1 = *(const ull*)&Bs[k][n0 + 2];
            ull b2 = *(const ull*)&Bs[k][n0 + 4];
            ull b3 = *(const ull*)&Bs[k][n0 + 6];
            float av[8] = {a0.x, a0.y, a0.z, a0.w, a1.x, a1.y, a1.z, a1.w};
#pragma unroll
            for (int i = 0; i < 8; i++) {
                ull a2 = pk2(av[i], av[i]);
                acc[i][0] = f2fma(a2, b0, acc[i][0]);
                acc[i][1] = f2fma(a2, b1, acc[i][1]);
                acc[i][2] = f2fma(a2, b2, acc[i][2]);
                acc[i][3] = f2fma(a2, b3, acc[i][3]);
            }
        }
        __syncthreads();
    }

#pragma unroll
    for (int i = 0; i < 8; i++) {
        float2 c0 = up2(acc[i][0]), c1 = up2(acc[i][1]);
        float2 c2 = up2(acc[i][2]), c3 = up2(acc[i][3]);
        float* cp = C + (size_t)(mBase + m0 + i) * N + nBase + n0;
        *(float4*)cp       = make_float4(c0.x, c0.y, c1.x, c1.y);
        *(float4*)(cp + 4) = make_float4(c2.x, c2.y, c3.x, c3.y);
    }
}

// ---------------------------------------------------------------------------
// Flash attention, fp32, causal. One q-row per thread (128 rows/CTA),
// K/V tiles 64x64 in smem (broadcast LDS reads), online softmax in 32-chunks.
// grid = (S/128, B*H), 128 threads.
// ---------------------------------------------------------------------------
__global__ __launch_bounds__(128) void flash_kernel(
    const float* __restrict__ Qp, const float* __restrict__ Kp,
    const float* __restrict__ Vp, float* __restrict__ Op)
{
    __shared__ __align__(16) float Ks[64 * 64];
    __shared__ __align__(16) float Vs[64 * 64];

    const int qt  = blockIdx.x;          // 0..15
    const int bh  = blockIdx.y;          // 0..63
    const int b   = bh >> 4;
    const int h   = bh & 15;
    const int tid = threadIdx.x;         // 0..127
    const int qs  = qt * 128 + tid;      // global q position

    const size_t rowOff = ((size_t)(b * S_ + qs)) * D_ + h * DH_;

    ull q2[32];
#pragma unroll
    for (int i = 0; i < 32; i++) q2[i] = *(const ull*)(Qp + rowOff + 2 * i);

    ull o2[32];
#pragma unroll
    for (int i = 0; i < 32; i++) o2[i] = 0ULL;

    float m = -INFINITY, l = 0.f;

    const int nkt = 2 * qt + 2;          // causal: k-tiles 0..2qt+1
    for (int kt = 0; kt < nkt; kt++) {
        const float* kb_ = Kp + ((size_t)(b * S_ + kt * 64)) * D_ + h * DH_;
        const float* vb_ = Vp + ((size_t)(b * S_ + kt * 64)) * D_ + h * DH_;
#pragma unroll
        for (int i = 0; i < 8; i++) {
            int f = i * 128 + tid;
            int r = f >> 4, c4 = (f & 15) << 2;
            *(float4*)(Ks + r * 64 + c4) = *(const float4*)(kb_ + (size_t)r * D_ + c4);
            *(float4*)(Vs + r * 64 + c4) = *(const float4*)(vb_ + (size_t)r * D_ + c4);
        }
        __syncthreads();

#pragma unroll
        for (int c = 0; c < 2; c++) {
            int kbase = kt * 64 + c * 32;
            if (kbase <= qs) {           // warp-uniform (32-aligned boundaries)
                float s[32];
#pragma unroll
                for (int j = 0; j < 32; j++) {
                    const ull* kr = (const ull*)(Ks + (c * 32 + j) * 64);
                    ull accA = 0ULL, accB = 0ULL;
#pragma unroll
                    for (int d = 0; d < 32; d += 2) {
                        accA = f2fma(q2[d],     kr[d],     accA);
                        accB = f2fma(q2[d + 1], kr[d + 1], accB);
                    }
                    float2 ra = up2(accA), rb = up2(accB);
                    float sv = (ra.x + ra.y + rb.x + rb.y) * 0.125f;
                    s[j] = (kbase + j > qs) ? -INFINITY : sv;
                }
                float mx = m;
#pragma unroll
                for (int j = 0; j < 32; j++) mx = fmaxf(mx, s[j]);
                float corr = __expf(m - mx);
                float ssum = 0.f;
#pragma unroll
                for (int j = 0; j < 32; j++) { s[j] = __expf(s[j] - mx); ssum += s[j]; }
                l = l * corr + ssum;
                m = mx;
                ull c2 = pk2(corr, corr);
#pragma unroll
                for (int d = 0; d < 32; d++) o2[d] = f2mul(o2[d], c2);
#pragma unroll
                for (int j = 0; j < 32; j++) {
                    ull p2 = pk2(s[j], s[j]);
                    const ull* vr = (const ull*)(Vs + (c * 32 + j) * 64);
#pragma unroll
                    for (int d = 0; d < 32; d++) o2[d] = f2fma(p2, vr[d], o2[d]);
                }
            }
        }
        __syncthreads();
    }

    float inv = 1.0f / l;
    ull i2 = pk2(inv, inv);
    float* orow = Op + rowOff;
#pragma unroll
    for (int d = 0; d < 32; d++) {
        float2 r = up2(f2mul(o2[d], i2));
        *(float2*)(orow + 2 * d) = r;
    }
}

// ---------------------------------------------------------------------------
extern "C" void kernel_launch(void* const* d_in, const int* in_sizes, int n_in,
                              void* d_out, int out_size)
{
    const float* Q  = (const float*)d_in[0];
    const float* Kx = (const float*)d_in[1];
    const float* Vx = (const float*)d_in[2];
    const float* Wq = (const float*)d_in[3];
    const float* Wk = (const float*)d_in[4];
    const float* Wv = (const float*)d_in[5];
    const float* Wo = (const float*)d_in[6];
    float* out = (float*)d_out;

    float *q, *k, *v, *o;
    cudaGetSymbolAddress((void**)&q, g_q);
    cudaGetSymbolAddress((void**)&k, g_k);
    cudaGetSymbolAddress((void**)&v, g_v);
    cudaGetSymbolAddress((void**)&o, g_o);

    dim3 gg(D_ / 128, MROWS / 128);   // (8, 64)
    sgemm_nt<<<gg, 256>>>(Q,  Wq, q, MROWS, D_, D_);
    sgemm_nt<<<gg, 256>>>(Kx, Wk, k, MROWS, D_, D_);
    sgemm_nt<<<gg, 256>>>(Vx, Wv, v, MROWS, D_, D_);

    flash_kernel<<<dim3(S_ / 128, B_ * H_), 128>>>(q, k, v, o);

    sgemm_nt<<<gg, 256>>>(o, Wo, out, MROWS, D_, D_);
}

// round 9
// speedup vs baseline: 1.0245x; 1.0151x over previous
#include <cuda_runtime.h>
#include <cstdint>
#include <math.h>

#define B_  4
#define S_  2048
#define D_  1024
#define H_  16
#define DH_ 64
#define MROWS (B_ * S_)
#define VPAD 68

typedef unsigned long long ull;

__device__ __forceinline__ ull pk2(float a, float b) {
    ull r; asm("mov.b64 %0, {%1, %2};" : "=l"(r) : "f"(a), "f"(b)); return r;
}
__device__ __forceinline__ float2 up2(ull v) {
    float2 r; asm("mov.b64 {%0, %1}, %2;" : "=f"(r.x), "=f"(r.y) : "l"(v)); return r;
}
__device__ __forceinline__ ull f2fma(ull a, ull b, ull c) {
    ull d; asm("fma.rn.f32x2 %0, %1, %2, %3;" : "=l"(d) : "l"(a), "l"(b), "l"(c)); return d;
}
__device__ __forceinline__ ull f2mul(ull a, ull b) {
    ull d; asm("mul.rn.f32x2 %0, %1, %2;" : "=l"(d) : "l"(a), "l"(b)); return d;
}

__device__ float g_q[MROWS * D_];
__device__ float g_k[MROWS * D_];
__device__ float g_v[MROWS * D_];
__device__ float g_o[MROWS * D_];

// ---------------------------------------------------------------------------
// GEMM: C[8192,1024] = A * W^T. 128x128 tile, 128 threads, 16x8 per thread.
// 0.75 B LDS per lane-FMA (crossbar 4x under FMA). Register prefetch.
// blockIdx.z picks one of up to 3 independent GEMMs.
// ---------------------------------------------------------------------------
__global__ __launch_bounds__(128, 2) void gemm128(
    const float* __restrict__ A0, const float* __restrict__ A1, const float* __restrict__ A2,
    const float* __restrict__ W0, const float* __restrict__ W1, const float* __restrict__ W2,
    float* __restrict__ C0, float* __restrict__ C1, float* __restrict__ C2)
{
    const float* A; const float* W; float* C;
    if (blockIdx.z == 0)      { A = A0; W = W0; C = C0; }
    else if (blockIdx.z == 1) { A = A1; W = W1; C = C1; }
    else                      { A = A2; W = W2; C = C2; }

    __shared__ __align__(16) float As[16][128];
    __shared__ __align__(16) float Bs[16][128];

    const int tid = threadIdx.x;
    const int m0  = (tid >> 4) << 4;     // 0..112
    const int n0  = (tid & 15) << 3;     // 0..120
    const size_t mBase = (size_t)blockIdx.y * 128;
    const size_t nBase = (size_t)blockIdx.x * 128;

    const float* aP = A + (mBase + tid) * D_;
    const float* wP = W + (nBase + tid) * D_;

    float4 pa[4], pb[4];
#pragma unroll
    for (int c = 0; c < 4; c++) {
        pa[c] = *(const float4*)(aP + 4 * c);
        pb[c] = *(const float4*)(wP + 4 * c);
    }

    ull acc[16][4];
#pragma unroll
    for (int i = 0; i < 16; i++)
#pragma unroll
        for (int j = 0; j < 4; j++) acc[i][j] = 0ULL;

    for (int kb = 0; kb < D_; kb += 16) {
#pragma unroll
        for (int c = 0; c < 4; c++) {
            As[4*c+0][tid] = pa[c].x; As[4*c+1][tid] = pa[c].y;
            As[4*c+2][tid] = pa[c].z; As[4*c+3][tid] = pa[c].w;
            Bs[4*c+0][tid] = pb[c].x; Bs[4*c+1][tid] = pb[c].y;
            Bs[4*c+2][tid] = pb[c].z; Bs[4*c+3][tid] = pb[c].w;
        }
        __syncthreads();
        if (kb + 16 < D_) {
            aP += 16; wP += 16;
#pragma unroll
            for (int c = 0; c < 4; c++) {
                pa[c] = *(const float4*)(aP + 4 * c);
                pb[c] = *(const float4*)(wP + 4 * c);
            }
        }
#pragma unroll
        for (int k = 0; k < 16; k++) {
            float av[16];
            *(float4*)&av[0]  = *(const float4*)&As[k][m0];
            *(float4*)&av[4]  = *(const float4*)&As[k][m0 + 4];
            *(float4*)&av[8]  = *(const float4*)&As[k][m0 + 8];
            *(float4*)&av[12] = *(const float4*)&As[k][m0 + 12];
            ulonglong2 b01 = *(const ulonglong2*)&Bs[k][n0];
            ulonglong2 b23 = *(const ulonglong2*)&Bs[k][n0 + 4];
#pragma unroll
            for (int i = 0; i < 16; i++) {
                ull a2 = pk2(av[i], av[i]);
                acc[i][0] = f2fma(a2, b01.x, acc[i][0]);
                acc[i][1] = f2fma(a2, b01.y, acc[i][1]);
                acc[i][2] = f2fma(a2, b23.x, acc[i][2]);
                acc[i][3] = f2fma(a2, b23.y, acc[i][3]);
            }
        }
        __syncthreads();
    }

#pragma unroll
    for (int i = 0; i < 16; i++) {
        float2 c0 = up2(acc[i][0]), c1 = up2(acc[i][1]);
        float2 c2 = up2(acc[i][2]), c3 = up2(acc[i][3]);
        float* cp = C + (mBase + m0 + i) * D_ + nBase + n0;
        *(float4*)cp       = make_float4(c0.x, c0.y, c1.x, c1.y);
        *(float4*)(cp + 4) = make_float4(c2.x, c2.y, c3.x, c3.y);
    }
}

// ---------------------------------------------------------------------------
// Flash v2: 256 threads, q-block 128, k-block 64, thread tile 4q x 8k.
// Score + PV as register-tiled GEMMs; P broadcast via shfl (width 8).
// smem: Qs d-major [64][128], Ks d-major [64][64], Vs [64][VPAD]. ~65KB dyn.
// ---------------------------------------------------------------------------
__global__ __launch_bounds__(256, 2) void flash_v2(
    const float* __restrict__ Qp, const float* __restrict__ Kp,
    const float* __restrict__ Vp, float* __restrict__ Op)
{
    extern __shared__ __align__(16) char smr[];
    float* Qs = (float*)smr;            // 64*128
    float* Ks = Qs + 64 * 128;          // 64*64
    float* Vs = Ks + 64 * 64;           // 64*VPAD

    const int tid = threadIdx.x;
    const int n0  = (tid & 7) << 3;     // k/d col offset 0..56
    const int m0  = (tid >> 3) << 2;    // q row offset 0..124
    const int bx  = gridDim.x - 1 - blockIdx.x;   // heavy blocks first
    const int qBase = bx * 128;
    const int b = blockIdx.y >> 4, h = blockIdx.y & 15;
    const size_t headOff = (size_t)b * S_ * D_ + (size_t)h * DH_;

    {   // Q -> smem (d-major), prescaled by 1/sqrt(DH)=0.125
        int qr = tid >> 1, dh = (tid & 1) * 32;
        const float* qs = Qp + headOff + (size_t)(qBase + qr) * D_ + dh;
#pragma unroll
        for (int c = 0; c < 8; c++) {
            float4 v = *(const float4*)(qs + 4 * c);
            Qs[(dh + 4*c + 0) * 128 + qr] = v.x * 0.125f;
            Qs[(dh + 4*c + 1) * 128 + qr] = v.y * 0.125f;
            Qs[(dh + 4*c + 2) * 128 + qr] = v.z * 0.125f;
            Qs[(dh + 4*c + 3) * 128 + qr] = v.w * 0.125f;
        }
    }

    ull o[4][4];
#pragma unroll
    for (int i = 0; i < 4; i++)
#pragma unroll
        for (int j = 0; j < 4; j++) o[i][j] = 0ULL;
    float mrow[4] = {-INFINITY, -INFINITY, -INFINITY, -INFINITY};
    float lrow[4] = {0.f, 0.f, 0.f, 0.f};

    const int kr = tid >> 2, dq = (tid & 3) << 4;
    const int nkt = 2 * bx + 2;

    for (int kt = 0; kt < nkt; kt++) {
        const float* kp = Kp + headOff + (size_t)(kt * 64 + kr) * D_ + dq;
        const float* vp = Vp + headOff + (size_t)(kt * 64 + kr) * D_ + dq;
        float4 kv[4], vv[4];
#pragma unroll
        for (int c = 0; c < 4; c++) { kv[c] = *(const float4*)(kp + 4*c); vv[c] = *(const float4*)(vp + 4*c); }
        __syncthreads();                 // prior tile fully consumed
#pragma unroll
        for (int c = 0; c < 4; c++) {
            Ks[(dq + 4*c + 0) * 64 + kr] = kv[c].x;
            Ks[(dq + 4*c + 1) * 64 + kr] = kv[c].y;
            Ks[(dq + 4*c + 2) * 64 + kr] = kv[c].z;
            Ks[(dq + 4*c + 3) * 64 + kr] = kv[c].w;
            *(float4*)&Vs[kr * VPAD + dq + 4*c] = vv[c];
        }
        __syncthreads();

        // ---- S = Q K^T (packed over k) ----
        ull s2[4][4];
#pragma unroll
        for (int i = 0; i < 4; i++)
#pragma unroll
            for (int j = 0; j < 4; j++) s2[i][j] = 0ULL;
        for (int d8 = 0; d8 < 8; d8++) {
#pragma unroll
            for (int dd = 0; dd < 8; dd++) {
                const int d = d8 * 8 + dd;
                float4 qv = *(const float4*)&Qs[d * 128 + m0];
                ulonglong2 k01 = *(const ulonglong2*)&Ks[d * 64 + n0];
                ulonglong2 k23 = *(const ulonglong2*)&Ks[d * 64 + n0 + 4];
                float qa[4] = {qv.x, qv.y, qv.z, qv.w};
#pragma unroll
                for (int i = 0; i < 4; i++) {
                    ull q2 = pk2(qa[i], qa[i]);
                    s2[i][0] = f2fma(q2, k01.x, s2[i][0]);
                    s2[i][1] = f2fma(q2, k01.y, s2[i][1]);
                    s2[i][2] = f2fma(q2, k23.x, s2[i][2]);
                    s2[i][3] = f2fma(q2, k23.y, s2[i][3]);
                }
            }
        }

        // ---- online softmax (8-lane groups) ----
        float sv[4][8];
        const bool bnd = (kt >= nkt - 2);
        const int kOff = kt * 64 + n0;
#pragma unroll
        for (int i = 0; i < 4; i++) {
#pragma unroll
            for (int j2 = 0; j2 < 4; j2++) {
                float2 u = up2(s2[i][j2]);
                sv[i][2*j2] = u.x; sv[i][2*j2+1] = u.y;
            }
            if (bnd) {
                int q = qBase + m0 + i;
#pragma unroll
                for (int j = 0; j < 8; j++)
                    if (kOff + j > q) sv[i][j] = -INFINITY;
            }
            float mx = sv[i][0];
#pragma unroll
            for (int j = 1; j < 8; j++) mx = fmaxf(mx, sv[i][j]);
            mx = fmaxf(mx, __shfl_xor_sync(0xffffffffu, mx, 1, 8));
            mx = fmaxf(mx, __shfl_xor_sync(0xffffffffu, mx, 2, 8));
            mx = fmaxf(mx, __shfl_xor_sync(0xffffffffu, mx, 4, 8));
            float nm = fmaxf(mrow[i], mx);
            float corr = __expf(mrow[i] - nm);
            mrow[i] = nm;
            float ss = 0.f;
#pragma unroll
            for (int j = 0; j < 8; j++) { float p = __expf(sv[i][j] - nm); sv[i][j] = p; ss += p; }
            ss += __shfl_xor_sync(0xffffffffu, ss, 1, 8);
            ss += __shfl_xor_sync(0xffffffffu, ss, 2, 8);
            ss += __shfl_xor_sync(0xffffffffu, ss, 4, 8);
            lrow[i] = lrow[i] * corr + ss;
            ull c2 = pk2(corr, corr);
#pragma unroll
            for (int j = 0; j < 4; j++) o[i][j] = f2mul(o[i][j], c2);
        }

        // ---- O += P V (P broadcast via shfl) ----
        for (int sl = 0; sl < 8; sl++) {
#pragma unroll
            for (int j = 0; j < 8; j++) {
                const int kl = sl * 8 + j;
                ulonglong2 v01 = *(const ulonglong2*)&Vs[kl * VPAD + n0];
                ulonglong2 v23 = *(const ulonglong2*)&Vs[kl * VPAD + n0 + 4];
#pragma unroll
                for (int i = 0; i < 4; i++) {
                    float p = __shfl_sync(0xffffffffu, sv[i][j], sl, 8);
                    ull p2 = pk2(p, p);
                    o[i][0] = f2fma(p2, v01.x, o[i][0]);
                    o[i][1] = f2fma(p2, v01.y, o[i][1]);
                    o[i][2] = f2fma(p2, v23.x, o[i][2]);
                    o[i][3] = f2fma(p2, v23.y, o[i][3]);
                }
            }
        }
    }

#pragma unroll
    for (int i = 0; i < 4; i++) {
        float inv = 1.0f / lrow[i];
        ull iv = pk2(inv, inv);
        float2 a = up2(f2mul(o[i][0], iv)), b2 = up2(f2mul(o[i][1], iv));
        float2 c = up2(f2mul(o[i][2], iv)), d2 = up2(f2mul(o[i][3], iv));
        float* op = Op + headOff + (size_t)(qBase + m0 + i) * D_ + n0;
        *(float4*)op       = make_float4(a.x, a.y, b2.x, b2.y);
        *(float4*)(op + 4) = make_float4(c.x, c.y, d2.x, d2.y);
    }
}

// ---------------------------------------------------------------------------
extern "C" void kernel_launch(void* const* d_in, const int* in_sizes, int n_in,
                              void* d_out, int out_size)
{
    const float* Q  = (const float*)d_in[0];
    const float* Kx = (const float*)d_in[1];
    const float* Vx = (const float*)d_in[2];
    const float* Wq = (const float*)d_in[3];
    const float* Wk = (const float*)d_in[4];
    const float* Wv = (const float*)d_in[5];
    const float* Wo = (const float*)d_in[6];
    float* out = (float*)d_out;

    float *q, *k, *v, *o;
    cudaGetSymbolAddress((void**)&q, g_q);
    cudaGetSymbolAddress((void**)&k, g_k);
    cudaGetSymbolAddress((void**)&v, g_v);
    cudaGetSymbolAddress((void**)&o, g_o);

    const int flashSmem = (64 * 128 + 64 * 64 + 64 * VPAD) * sizeof(float); // 66560
    cudaFuncSetAttribute(flash_v2, cudaFuncAttributeMaxDynamicSharedMemorySize, flashSmem);

    // fused Q/K/V projections
    gemm128<<<dim3(8, 64, 3), 128>>>(Q, Kx, Vx, Wq, Wk, Wv, q, k, v);

    flash_v2<<<dim3(S_ / 128, B_ * H_), 256, flashSmem>>>(q, k, v, o);

    // output projection
    gemm128<<<dim3(8, 64, 1), 128>>>(o, o, o, Wo, Wo, Wo, out, out, out);
}